// round 7
// baseline (speedup 1.0000x reference)
#include <cuda_runtime.h>
#include <cstdint>
#include <cstddef>

// Problem constants
#define MTOT 16384      // B*S = 4*4096
#define HDIM 2048       // H
#define CHID 512        // CH
#define KIN  6144       // 3*H

// Scratch (static device globals -- allocation-free rule). Same set as the
// proven Round-0 kernel: nothing new.
__device__ float2 g_stats[3 * MTOT];                 // (mu, rstd) per (tensor,row)
__device__ float  g_hidden[(size_t)MTOT * CHID];     // GEMM1 output (post-GELU), fp32

__device__ __forceinline__ float to_tf32(float x) {
    uint32_t o;
    asm("cvt.rna.tf32.f32 %0, %1;" : "=r"(o) : "f"(x));
    return __uint_as_float(o);
}

__device__ __forceinline__ float gelu_exact(float x) {
    return 0.5f * x * (1.0f + erff(x * 0.70710678118654752440f));
}

// ---------------------------------------------------------------------------
// Kernel 1: per-row LayerNorm statistics (EXACT copy of the passing R0 kernel)
// grid = (MTOT, 3), block = 256.
// ---------------------------------------------------------------------------
__global__ void __launch_bounds__(256) ln_stats_kernel(
    const float* __restrict__ xp,
    const float* __restrict__ xu,
    const float* __restrict__ xz)
{
    const int m = blockIdx.x;
    const int t = blockIdx.y;
    const float* X = (t == 0) ? xp : ((t == 1) ? xu : xz);
    const float4* row = (const float4*)(X + (size_t)m * HDIM);

    float s = 0.f, sq = 0.f;
#pragma unroll
    for (int j = 0; j < 2; j++) {
        float4 v = row[threadIdx.x + j * 256];
        s  += v.x + v.y + v.z + v.w;
        sq += v.x * v.x + v.y * v.y + v.z * v.z + v.w * v.w;
    }

    __shared__ float s1[256], s2[256];
    s1[threadIdx.x] = s;
    s2[threadIdx.x] = sq;
    __syncthreads();
#pragma unroll
    for (int o = 128; o > 0; o >>= 1) {
        if (threadIdx.x < o) {
            s1[threadIdx.x] += s1[threadIdx.x + o];
            s2[threadIdx.x] += s2[threadIdx.x + o];
        }
        __syncthreads();
    }
    if (threadIdx.x == 0) {
        float mu  = s1[0] * (1.0f / HDIM);
        float var = s2[0] * (1.0f / HDIM) - mu * mu;
        g_stats[t * MTOT + m] = make_float2(mu, rsqrtf(var + 1e-5f));
    }
}

// ---------------------------------------------------------------------------
// Tiled tf32 mma.sync GEMM:  C[M,N] = A[M,K] @ W[N,K]^T  (+bias, opt GELU)
// BM=128, BN=128, BK=32, 256 threads = 8 warps (4 along M x 2 along N),
// warp tile 32x64 = 2x8 m16n8k8 mma tiles. Register double-buffered:
// next tile's LDGs issue before the current tile's mma block.
// Fragment algebra is byte-identical to the passing Round-0 kernel.
// ---------------------------------------------------------------------------
template<bool LN_A, bool GELU, int N, int K>
__global__ void __launch_bounds__(256) gemm_tf32_kernel(
    const float* __restrict__ x0, const float* __restrict__ x1, const float* __restrict__ x2,
    const float* __restrict__ g0, const float* __restrict__ g1, const float* __restrict__ g2,
    const float* __restrict__ c0, const float* __restrict__ c1, const float* __restrict__ c2,
    const float* __restrict__ W,      // [N][K] row-major (k contiguous)
    const float* __restrict__ bias,   // [N]
    float* __restrict__ Cout)         // [M][N]
{
    constexpr int LDS_ = 36;          // BK + 4 pad; row stride 144B (16B-aligned)
    __shared__ __align__(16) float As[128 * LDS_];   // 18 KB
    __shared__ __align__(16) float Bs[128 * LDS_];   // 18 KB

    const int bm   = blockIdx.y * 128;
    const int bn   = blockIdx.x * 128;
    const int tid  = threadIdx.x;
    const int lane = tid & 31;
    const int warp = tid >> 5;
    const int warpM = warp & 3;       // 0..3 -> 32-row slices
    const int warpN = warp >> 2;      // 0..1 -> 64-col slices

    // per-thread staging geometry (same derivation as R0):
    // i = tid + j*256  ->  r = (tid>>3) + j*32 (row),  kv = (tid&7)*4 (k cols)
    const int rbase = tid >> 3;
    const int kv    = (tid & 7) << 2;

    float acc[2][8][4];
#pragma unroll
    for (int i = 0; i < 2; i++)
#pragma unroll
        for (int j = 0; j < 8; j++)
#pragma unroll
            for (int r = 0; r < 4; r++) acc[i][j][r] = 0.f;

    // register tile buffers
    float4 rX[4], rW[4], rG, rBb;
    float2 rst[4];

    // ---- tile loader: global -> registers ----
    auto ldg_tile = [&](int k0) {
        if (LN_A) {
            const int t = k0 >> 11;             // which tensor (2048-col blocks)
            const int kb = (k0 & 2047) + kv;
            const float* X  = (t == 0) ? x0 : ((t == 1) ? x1 : x2);
            const float* G  = (t == 0) ? g0 : ((t == 1) ? g1 : g2);
            const float* Bb = (t == 0) ? c0 : ((t == 1) ? c1 : c2);
            rG  = *(const float4*)(G + kb);
            rBb = *(const float4*)(Bb + kb);
#pragma unroll
            for (int j = 0; j < 4; j++) {
                const int m = bm + rbase + j * 32;
                rst[j] = g_stats[t * MTOT + m];
                rX[j]  = *(const float4*)(X + (size_t)m * HDIM + kb);
            }
        } else {
#pragma unroll
            for (int j = 0; j < 4; j++) {
                const int m = bm + rbase + j * 32;
                rX[j] = *(const float4*)(g_hidden + (size_t)m * K + k0 + kv);
            }
        }
#pragma unroll
        for (int j = 0; j < 4; j++) {
            const int n = bn + rbase + j * 32;
            rW[j] = *(const float4*)(W + (size_t)n * K + k0 + kv);
        }
    };

    // ---- registers -> shared (with LN + tf32 rounding) ----
    auto sts_tile = [&]() {
#pragma unroll
        for (int j = 0; j < 4; j++) {
            const int r = rbase + j * 32;
            float4 v = rX[j];
            if (LN_A) {
                const float mu = rst[j].x, rs = rst[j].y;
                v.x = to_tf32((v.x - mu) * rs * rG.x + rBb.x);
                v.y = to_tf32((v.y - mu) * rs * rG.y + rBb.y);
                v.z = to_tf32((v.z - mu) * rs * rG.z + rBb.z);
                v.w = to_tf32((v.w - mu) * rs * rG.w + rBb.w);
            } else {
                v.x = to_tf32(v.x); v.y = to_tf32(v.y);
                v.z = to_tf32(v.z); v.w = to_tf32(v.w);
            }
            *(float4*)(&As[r * LDS_ + kv]) = v;
        }
#pragma unroll
        for (int j = 0; j < 4; j++) {
            const int r = rbase + j * 32;
            float4 v = rW[j];
            v.x = to_tf32(v.x); v.y = to_tf32(v.y);
            v.z = to_tf32(v.z); v.w = to_tf32(v.w);
            *(float4*)(&Bs[r * LDS_ + kv]) = v;
        }
    };

    constexpr int NT = K / 32;
    ldg_tile(0);

    for (int i = 0; i < NT; i++) {
        __syncthreads();                  // consumers done with smem (no-op at i=0)
        sts_tile();
        __syncthreads();
        if (i + 1 < NT) ldg_tile((i + 1) * 32);   // overlap with mma below

        // ---- mainloop over 4 k-steps of 8 (R0-identical fragment algebra) ----
#pragma unroll
        for (int kk = 0; kk < 32; kk += 8) {
            uint32_t a[2][4], b[8][2];
            const int ac = kk + (lane & 3);
            const int ar = warpM * 32 + (lane >> 2);
#pragma unroll
            for (int mt = 0; mt < 2; mt++) {
                int r = ar + mt * 16;
                a[mt][0] = __float_as_uint(As[r * LDS_ + ac]);
                a[mt][1] = __float_as_uint(As[(r + 8) * LDS_ + ac]);
                a[mt][2] = __float_as_uint(As[r * LDS_ + ac + 4]);
                a[mt][3] = __float_as_uint(As[(r + 8) * LDS_ + ac + 4]);
            }
            const int br = warpN * 64 + (lane >> 2);
#pragma unroll
            for (int nt = 0; nt < 8; nt++) {
                int r = br + nt * 8;
                b[nt][0] = __float_as_uint(Bs[r * LDS_ + ac]);
                b[nt][1] = __float_as_uint(Bs[r * LDS_ + ac + 4]);
            }
#pragma unroll
            for (int mt = 0; mt < 2; mt++)
#pragma unroll
                for (int nt = 0; nt < 8; nt++)
                    asm volatile(
                        "mma.sync.aligned.m16n8k8.row.col.f32.tf32.tf32.f32 "
                        "{%0,%1,%2,%3}, {%4,%5,%6,%7}, {%8,%9}, {%0,%1,%2,%3};\n"
                        : "+f"(acc[mt][nt][0]), "+f"(acc[mt][nt][1]),
                          "+f"(acc[mt][nt][2]), "+f"(acc[mt][nt][3])
                        : "r"(a[mt][0]), "r"(a[mt][1]), "r"(a[mt][2]), "r"(a[mt][3]),
                          "r"(b[nt][0]), "r"(b[nt][1]));
        }
    }

    // ---- epilogue (R0-identical mapping, nt extended to 8) ----
    float* Cdst = GELU ? g_hidden : Cout;
#pragma unroll
    for (int mt = 0; mt < 2; mt++) {
        int row = bm + warpM * 32 + mt * 16 + (lane >> 2);
#pragma unroll
        for (int nt = 0; nt < 8; nt++) {
            int col = bn + warpN * 64 + nt * 8 + ((lane & 3) << 1);
            float bs0 = bias[col], bs1 = bias[col + 1];
            float v0 = acc[mt][nt][0] + bs0;
            float v1 = acc[mt][nt][1] + bs1;
            float v2 = acc[mt][nt][2] + bs0;
            float v3 = acc[mt][nt][3] + bs1;
            if (GELU) {
                v0 = gelu_exact(v0); v1 = gelu_exact(v1);
                v2 = gelu_exact(v2); v3 = gelu_exact(v3);
            }
            Cdst[(size_t)row * N + col]           = v0;
            Cdst[(size_t)row * N + col + 1]       = v1;
            Cdst[(size_t)(row + 8) * N + col]     = v2;
            Cdst[(size_t)(row + 8) * N + col + 1] = v3;
        }
    }
}

// ---------------------------------------------------------------------------
extern "C" void kernel_launch(void* const* d_in, const int* in_sizes, int n_in,
                              void* d_out, int out_size)
{
    const float* u_t    = (const float*)d_in[0];
    const float* z_t    = (const float*)d_in[1];
    const float* prev   = (const float*)d_in[2];
    const float* prev_g = (const float*)d_in[3];
    const float* prev_b = (const float*)d_in[4];
    const float* u_g    = (const float*)d_in[5];
    const float* u_b    = (const float*)d_in[6];
    const float* z_g    = (const float*)d_in[7];
    const float* z_b    = (const float*)d_in[8];
    const float* W1     = (const float*)d_in[9];
    const float* b1     = (const float*)d_in[10];
    const float* W2     = (const float*)d_in[11];
    const float* b2     = (const float*)d_in[12];
    float* out = (float*)d_out;

    // 1) LN statistics for the three branches
    ln_stats_kernel<<<dim3(MTOT, 3), 256>>>(prev, u_t, z_t);

    // 2) GEMM1: hidden = gelu(LN-concat @ W1^T + b1)   [16384 x 512]
    gemm_tf32_kernel<true, true, CHID, KIN><<<dim3(CHID / 128, MTOT / 128), 256>>>(
        prev, u_t, z_t,
        prev_g, u_g, z_g,
        prev_b, u_b, z_b,
        W1, b1, nullptr);

    // 3) GEMM2: out = hidden @ W2^T + b2               [16384 x 2048]
    gemm_tf32_kernel<false, false, HDIM, CHID><<<dim3(HDIM / 128, MTOT / 128), 256>>>(
        nullptr, nullptr, nullptr,
        nullptr, nullptr, nullptr,
        nullptr, nullptr, nullptr,
        W2, b2, out);
}

// round 8
// speedup vs baseline: 2.2086x; 2.2086x over previous
#include <cuda_runtime.h>
#include <cuda_fp16.h>
#include <cstdint>
#include <cstddef>

// Problem constants
#define MTOT 16384      // B*S = 4*4096
#define HDIM 2048       // H
#define CHID 512        // CH
#define KIN  6144       // 3*H

// Scratch: EXACT same global set as the passing R0/R7 kernels. Nothing new.
__device__ float2 g_stats[3 * MTOT];                 // (mu, rstd) per (tensor,row)
__device__ float  g_hidden[(size_t)MTOT * CHID];     // GEMM1 output (post-GELU), fp32

__device__ __forceinline__ float gelu_exact(float x) {
    return 0.5f * x * (1.0f + erff(x * 0.70710678118654752440f));
}

// ---------------------------------------------------------------------------
// Kernel 1: per-row LayerNorm statistics (EXACT copy of the passing kernel)
// ---------------------------------------------------------------------------
__global__ void __launch_bounds__(256) ln_stats_kernel(
    const float* __restrict__ xp,
    const float* __restrict__ xu,
    const float* __restrict__ xz)
{
    const int m = blockIdx.x;
    const int t = blockIdx.y;
    const float* X = (t == 0) ? xp : ((t == 1) ? xu : xz);
    const float4* row = (const float4*)(X + (size_t)m * HDIM);

    float s = 0.f, sq = 0.f;
#pragma unroll
    for (int j = 0; j < 2; j++) {
        float4 v = row[threadIdx.x + j * 256];
        s  += v.x + v.y + v.z + v.w;
        sq += v.x * v.x + v.y * v.y + v.z * v.z + v.w * v.w;
    }

    __shared__ float s1[256], s2[256];
    s1[threadIdx.x] = s;
    s2[threadIdx.x] = sq;
    __syncthreads();
#pragma unroll
    for (int o = 128; o > 0; o >>= 1) {
        if (threadIdx.x < o) {
            s1[threadIdx.x] += s1[threadIdx.x + o];
            s2[threadIdx.x] += s2[threadIdx.x + o];
        }
        __syncthreads();
    }
    if (threadIdx.x == 0) {
        float mu  = s1[0] * (1.0f / HDIM);
        float var = s2[0] * (1.0f / HDIM) - mu * mu;
        g_stats[t * MTOT + m] = make_float2(mu, rsqrtf(var + 1e-5f));
    }
}

// ---------------------------------------------------------------------------
// Tiled fp16 mma.sync GEMM:  C[M,N] = A[M,K] @ W[N,K]^T  (+bias, opt GELU)
// Skeleton identical to the passing R7 kernel. Deltas confined to:
//   * smem tiles stored as fp16 (converted in registers at STS time)
//   * mma.m16n8k16.f16 (C-fragment mapping identical to m16n8k8)
//   * 2-stage smem ping-pong -> single __syncthreads per K tile
// BM=128, BN=128, BK=32, 256 threads = 8 warps (4 M x 2 N),
// warp tile 32x64 = 2x8 mma tiles, 2 k-steps of 16 per BK tile.
// ---------------------------------------------------------------------------
#define ROWB  80                       // 64B data (32 halfs) + 16B pad
#define A_ST  (128 * ROWB)             // 10240 B
#define STAGE (2 * A_ST)               // A + B per stage = 20480 B

template<bool LN_A, bool GELU, int N, int K>
__global__ void __launch_bounds__(256) gemm_fp16_kernel(
    const float* __restrict__ x0, const float* __restrict__ x1, const float* __restrict__ x2,
    const float* __restrict__ g0, const float* __restrict__ g1, const float* __restrict__ g2,
    const float* __restrict__ c0, const float* __restrict__ c1, const float* __restrict__ c2,
    const float* __restrict__ W,      // [N][K] row-major (k contiguous)
    const float* __restrict__ bias,   // [N]
    float* __restrict__ Cout)         // [M][N]
{
    __shared__ __align__(16) unsigned char smem[2 * STAGE];   // 40 KB static

    const int bm   = blockIdx.y * 128;
    const int bn   = blockIdx.x * 128;
    const int tid  = threadIdx.x;
    const int lane = tid & 31;
    const int warp = tid >> 5;
    const int warpM = warp & 3;       // 0..3 -> 32-row slices
    const int warpN = warp >> 1 >> 1; // 0..1 -> 64-col slices  (== warp>>2)
    const int g = lane >> 2;          // row within 8-group
    const int t = lane & 3;           // k-pair index

    // staging geometry (R7-identical): r = tid>>3 (+j*32), kv = (tid&7)*4 K-cols
    const int rbase = tid >> 3;
    const int kv    = (tid & 7) << 2;

    float acc[2][8][4];
#pragma unroll
    for (int i = 0; i < 2; i++)
#pragma unroll
        for (int j = 0; j < 8; j++)
#pragma unroll
            for (int r = 0; r < 4; r++) acc[i][j][r] = 0.f;

    // register tile buffers (R7-identical)
    float4 rX[4], rW[4], rG, rBb;
    float2 rst[4];

    auto ldg_tile = [&](int k0) {
        if (LN_A) {
            const int tt = k0 >> 11;            // which tensor (2048-col blocks)
            const int kb = (k0 & 2047) + kv;
            const float* X  = (tt == 0) ? x0 : ((tt == 1) ? x1 : x2);
            const float* G  = (tt == 0) ? g0 : ((tt == 1) ? g1 : g2);
            const float* Bb = (tt == 0) ? c0 : ((tt == 1) ? c1 : c2);
            rG  = *(const float4*)(G + kb);
            rBb = *(const float4*)(Bb + kb);
#pragma unroll
            for (int j = 0; j < 4; j++) {
                const int m = bm + rbase + j * 32;
                rst[j] = g_stats[tt * MTOT + m];
                rX[j]  = *(const float4*)(X + (size_t)m * HDIM + kb);
            }
        } else {
#pragma unroll
            for (int j = 0; j < 4; j++) {
                const int m = bm + rbase + j * 32;
                rX[j] = *(const float4*)(g_hidden + (size_t)m * K + k0 + kv);
            }
        }
#pragma unroll
        for (int j = 0; j < 4; j++) {
            const int n = bn + rbase + j * 32;
            rW[j] = *(const float4*)(W + (size_t)n * K + k0 + kv);
        }
    };

    // registers -> shared, converting to fp16 (LN applied on the A side)
    auto sts_tile = [&](int buf) {
        unsigned char* As = smem + buf * STAGE;
        unsigned char* Bs = As + A_ST;
#pragma unroll
        for (int j = 0; j < 4; j++) {
            const int r = rbase + j * 32;
            float4 v = rX[j];
            if (LN_A) {
                const float mu = rst[j].x, rs = rst[j].y;
                v.x = (v.x - mu) * rs * rG.x + rBb.x;
                v.y = (v.y - mu) * rs * rG.y + rBb.y;
                v.z = (v.z - mu) * rs * rG.z + rBb.z;
                v.w = (v.w - mu) * rs * rG.w + rBb.w;
            }
            __half2 h0 = __floats2half2_rn(v.x, v.y);
            __half2 h1 = __floats2half2_rn(v.z, v.w);
            *(uint2*)(As + r * ROWB + kv * 2) =
                make_uint2(*(uint32_t*)&h0, *(uint32_t*)&h1);
        }
#pragma unroll
        for (int j = 0; j < 4; j++) {
            const int r = rbase + j * 32;
            float4 v = rW[j];
            __half2 h0 = __floats2half2_rn(v.x, v.y);
            __half2 h1 = __floats2half2_rn(v.z, v.w);
            *(uint2*)(Bs + r * ROWB + kv * 2) =
                make_uint2(*(uint32_t*)&h0, *(uint32_t*)&h1);
        }
    };

    constexpr int NT = K / 32;

    // prologue: tile 0 staged, tile 1 in registers
    ldg_tile(0);
    sts_tile(0);
    __syncthreads();
    if (NT > 1) ldg_tile(32);

    for (int i = 0; i < NT; i++) {
        if (i + 1 < NT) sts_tile((i + 1) & 1);        // stage next (other buffer)
        if (i + 2 < NT) ldg_tile((i + 2) * 32);       // prefetch next-next

        const unsigned char* As = smem + (i & 1) * STAGE;
        const unsigned char* Bs = As + A_ST;
#pragma unroll
        for (int kk = 0; kk < 2; kk++) {              // two k16 steps
            const int kb = kk * 32 + t * 4;           // byte offset of k pair
            uint32_t a[2][4], b[8][2];
#pragma unroll
            for (int mt = 0; mt < 2; mt++) {
                const unsigned char* p = As + (warpM * 32 + mt * 16 + g) * ROWB + kb;
                a[mt][0] = *(const uint32_t*)(p);
                a[mt][1] = *(const uint32_t*)(p + 8 * ROWB);
                a[mt][2] = *(const uint32_t*)(p + 16);
                a[mt][3] = *(const uint32_t*)(p + 8 * ROWB + 16);
            }
#pragma unroll
            for (int nt = 0; nt < 8; nt++) {
                const unsigned char* p = Bs + (warpN * 64 + nt * 8 + g) * ROWB + kb;
                b[nt][0] = *(const uint32_t*)(p);
                b[nt][1] = *(const uint32_t*)(p + 16);
            }
#pragma unroll
            for (int mt = 0; mt < 2; mt++)
#pragma unroll
                for (int nt = 0; nt < 8; nt++)
                    asm volatile(
                        "mma.sync.aligned.m16n8k16.row.col.f32.f16.f16.f32 "
                        "{%0,%1,%2,%3}, {%4,%5,%6,%7}, {%8,%9}, {%0,%1,%2,%3};\n"
                        : "+f"(acc[mt][nt][0]), "+f"(acc[mt][nt][1]),
                          "+f"(acc[mt][nt][2]), "+f"(acc[mt][nt][3])
                        : "r"(a[mt][0]), "r"(a[mt][1]), "r"(a[mt][2]), "r"(a[mt][3]),
                          "r"(b[nt][0]), "r"(b[nt][1]));
        }
        __syncthreads();
    }

    // ---- epilogue (mapping identical to passing R0/R7) ----
    float* Cdst = GELU ? g_hidden : Cout;
#pragma unroll
    for (int mt = 0; mt < 2; mt++) {
        int row = bm + warpM * 32 + mt * 16 + g;
#pragma unroll
        for (int nt = 0; nt < 8; nt++) {
            int col = bn + warpN * 64 + nt * 8 + (t << 1);
            float bs0 = bias[col], bs1 = bias[col + 1];
            float v0 = acc[mt][nt][0] + bs0;
            float v1 = acc[mt][nt][1] + bs1;
            float v2 = acc[mt][nt][2] + bs0;
            float v3 = acc[mt][nt][3] + bs1;
            if (GELU) {
                v0 = gelu_exact(v0); v1 = gelu_exact(v1);
                v2 = gelu_exact(v2); v3 = gelu_exact(v3);
            }
            Cdst[(size_t)row * N + col]           = v0;
            Cdst[(size_t)row * N + col + 1]       = v1;
            Cdst[(size_t)(row + 8) * N + col]     = v2;
            Cdst[(size_t)(row + 8) * N + col + 1] = v3;
        }
    }
}

// ---------------------------------------------------------------------------
extern "C" void kernel_launch(void* const* d_in, const int* in_sizes, int n_in,
                              void* d_out, int out_size)
{
    const float* u_t    = (const float*)d_in[0];
    const float* z_t    = (const float*)d_in[1];
    const float* prev   = (const float*)d_in[2];
    const float* prev_g = (const float*)d_in[3];
    const float* prev_b = (const float*)d_in[4];
    const float* u_g    = (const float*)d_in[5];
    const float* u_b    = (const float*)d_in[6];
    const float* z_g    = (const float*)d_in[7];
    const float* z_b    = (const float*)d_in[8];
    const float* W1     = (const float*)d_in[9];
    const float* b1     = (const float*)d_in[10];
    const float* W2     = (const float*)d_in[11];
    const float* b2     = (const float*)d_in[12];
    float* out = (float*)d_out;

    // 1) LN statistics for the three branches
    ln_stats_kernel<<<dim3(MTOT, 3), 256>>>(prev, u_t, z_t);

    // 2) GEMM1: hidden = gelu(LN-concat @ W1^T + b1)   [16384 x 512]
    gemm_fp16_kernel<true, true, CHID, KIN><<<dim3(CHID / 128, MTOT / 128), 256>>>(
        prev, u_t, z_t,
        prev_g, u_g, z_g,
        prev_b, u_b, z_b,
        W1, b1, nullptr);

    // 3) GEMM2: out = hidden @ W2^T + b2               [16384 x 2048]
    gemm_fp16_kernel<false, false, HDIM, CHID><<<dim3(HDIM / 128, MTOT / 128), 256>>>(
        nullptr, nullptr, nullptr,
        nullptr, nullptr, nullptr,
        nullptr, nullptr, nullptr,
        W2, b2, out);
}

// round 9
// speedup vs baseline: 2.2610x; 1.0237x over previous
#include <cuda_runtime.h>
#include <cuda_fp16.h>
#include <cstdint>
#include <cstddef>

// Problem constants
#define MTOT 16384      // B*S = 4*4096
#define HDIM 2048       // H
#define CHID 512        // CH
#define KIN  6144       // 3*H

// Scratch: EXACT same global set as all passing kernels. g_hidden is reused
// as fp16 storage via pointer cast (16.8 MB used of its 33.5 MB).
__device__ float2 g_stats[3 * MTOT];
__device__ float  g_hidden[(size_t)MTOT * CHID];

__device__ __forceinline__ float gelu_exact(float x) {
    return 0.5f * x * (1.0f + erff(x * 0.70710678118654752440f));
}
__device__ __forceinline__ uint32_t smem_u32(const void* p) {
    uint32_t a;
    asm("{ .reg .u64 t; cvta.to.shared.u64 t, %1; cvt.u32.u64 %0, t; }" : "=r"(a) : "l"(p));
    return a;
}

// ---------------------------------------------------------------------------
// Kernel 1: per-row LayerNorm statistics (EXACT copy of the passing kernel)
// ---------------------------------------------------------------------------
__global__ void __launch_bounds__(256) ln_stats_kernel(
    const float* __restrict__ xp,
    const float* __restrict__ xu,
    const float* __restrict__ xz)
{
    const int m = blockIdx.x;
    const int t = blockIdx.y;
    const float* X = (t == 0) ? xp : ((t == 1) ? xu : xz);
    const float4* row = (const float4*)(X + (size_t)m * HDIM);

    float s = 0.f, sq = 0.f;
#pragma unroll
    for (int j = 0; j < 2; j++) {
        float4 v = row[threadIdx.x + j * 256];
        s  += v.x + v.y + v.z + v.w;
        sq += v.x * v.x + v.y * v.y + v.z * v.z + v.w * v.w;
    }

    __shared__ float s1[256], s2[256];
    s1[threadIdx.x] = s;
    s2[threadIdx.x] = sq;
    __syncthreads();
#pragma unroll
    for (int o = 128; o > 0; o >>= 1) {
        if (threadIdx.x < o) {
            s1[threadIdx.x] += s1[threadIdx.x + o];
            s2[threadIdx.x] += s2[threadIdx.x + o];
        }
        __syncthreads();
    }
    if (threadIdx.x == 0) {
        float mu  = s1[0] * (1.0f / HDIM);
        float var = s2[0] * (1.0f / HDIM) - mu * mu;
        g_stats[t * MTOT + m] = make_float2(mu, rsqrtf(var + 1e-5f));
    }
}

// ---------------------------------------------------------------------------
// Tiled fp16 mma GEMM, R8 skeleton. Deltas this round:
//   * ldmatrix.m8n8.x4 fragment loads (6 issues/k-step vs 24 LDS)
//   * A-source for GEMM2 is fp16 (g_hidden reinterpreted); GEMM1 epilogue
//     writes fp16 hidden.
// BM=128, BN=128, BK=32, 256 threads = 8 warps (4 M x 2 N),
// warp tile 32x64 = 2x8 m16n8k16 tiles, 2 k-steps per BK tile.
// ---------------------------------------------------------------------------
#define ROWB  80                       // 64B data (32 halfs) + 16B pad
#define A_ST  (128 * ROWB)             // 10240 B
#define STAGE (2 * A_ST)               // A + B per stage = 20480 B

template<bool LN_A, bool GELU, int N, int K>
__global__ void __launch_bounds__(256) gemm_fp16_kernel(
    const float* __restrict__ x0, const float* __restrict__ x1, const float* __restrict__ x2,
    const float* __restrict__ g0, const float* __restrict__ g1, const float* __restrict__ g2,
    const float* __restrict__ c0, const float* __restrict__ c1, const float* __restrict__ c2,
    const float* __restrict__ W,      // [N][K] row-major fp32
    const float* __restrict__ bias,   // [N]
    float* __restrict__ Cout)         // [M][N] fp32 (final output)
{
    __shared__ __align__(16) unsigned char smem[2 * STAGE];   // 40 KB static

    const int bm   = blockIdx.y * 128;
    const int bn   = blockIdx.x * 128;
    const int tid  = threadIdx.x;
    const int lane = tid & 31;
    const int warp = tid >> 5;
    const int warpM = warp & 3;       // 0..3 -> 32-row slices
    const int warpN = warp >> 2;      // 0..1 -> 64-col slices
    const int g = lane >> 2;          // row within 8-group (epilogue)
    const int t = lane & 3;           // k-pair index (epilogue)

    // staging geometry: r = tid>>3 (+j*32), kv = (tid&7)*4 K-cols
    const int rbase = tid >> 3;
    const int kv    = (tid & 7) << 2;

    // ldmatrix source addresses (per-lane), within current stage buffer:
    // A, per mt: row = warpM*32 + mt*16 + (lane&15), k-half = (lane>>4)*16B
    const uint32_t sb = smem_u32(smem);
    const uint32_t a_lm = sb + (uint32_t)((warpM * 32 + (lane & 15)) * ROWB + (lane >> 4) * 16);
    // B, per nt-pair: quad q = lane>>3; n-row = warpN*64 + nt*8 + (q>>1)*8 + (lane&7),
    // k-half = (q&1)*16B
    const int q = lane >> 3;
    const uint32_t b_lm = sb + A_ST +
        (uint32_t)((warpN * 64 + (q >> 1) * 8 + (lane & 7)) * ROWB + (q & 1) * 16);

    float acc[2][8][4];
#pragma unroll
    for (int i = 0; i < 2; i++)
#pragma unroll
        for (int j = 0; j < 8; j++)
#pragma unroll
            for (int r = 0; r < 4; r++) acc[i][j][r] = 0.f;

    // register tile buffers
    float4 rX[4], rW[4], rG, rBb;
    uint2  rXh[4];                    // fp16 A source path (GEMM2)
    float2 rst[4];

    auto ldg_tile = [&](int k0) {
        if (LN_A) {
            const int tt = k0 >> 11;
            const int kb = (k0 & 2047) + kv;
            const float* X  = (tt == 0) ? x0 : ((tt == 1) ? x1 : x2);
            const float* G  = (tt == 0) ? g0 : ((tt == 1) ? g1 : g2);
            const float* Bb = (tt == 0) ? c0 : ((tt == 1) ? c1 : c2);
            rG  = *(const float4*)(G + kb);
            rBb = *(const float4*)(Bb + kb);
#pragma unroll
            for (int j = 0; j < 4; j++) {
                const int m = bm + rbase + j * 32;
                rst[j] = g_stats[tt * MTOT + m];
                rX[j]  = *(const float4*)(X + (size_t)m * HDIM + kb);
            }
        } else {
            const __half* Ah = (const __half*)g_hidden;
#pragma unroll
            for (int j = 0; j < 4; j++) {
                const int m = bm + rbase + j * 32;
                rXh[j] = *(const uint2*)(Ah + (size_t)m * K + k0 + kv);
            }
        }
#pragma unroll
        for (int j = 0; j < 4; j++) {
            const int n = bn + rbase + j * 32;
            rW[j] = *(const float4*)(W + (size_t)n * K + k0 + kv);
        }
    };

    auto sts_tile = [&](int buf) {
        unsigned char* As = smem + buf * STAGE;
        unsigned char* Bs = As + A_ST;
#pragma unroll
        for (int j = 0; j < 4; j++) {
            const int r = rbase + j * 32;
            if (LN_A) {
                float4 v = rX[j];
                const float mu = rst[j].x, rs = rst[j].y;
                v.x = (v.x - mu) * rs * rG.x + rBb.x;
                v.y = (v.y - mu) * rs * rG.y + rBb.y;
                v.z = (v.z - mu) * rs * rG.z + rBb.z;
                v.w = (v.w - mu) * rs * rG.w + rBb.w;
                __half2 h0 = __floats2half2_rn(v.x, v.y);
                __half2 h1 = __floats2half2_rn(v.z, v.w);
                *(uint2*)(As + r * ROWB + kv * 2) =
                    make_uint2(*(uint32_t*)&h0, *(uint32_t*)&h1);
            } else {
                *(uint2*)(As + r * ROWB + kv * 2) = rXh[j];
            }
        }
#pragma unroll
        for (int j = 0; j < 4; j++) {
            const int r = rbase + j * 32;
            float4 v = rW[j];
            __half2 h0 = __floats2half2_rn(v.x, v.y);
            __half2 h1 = __floats2half2_rn(v.z, v.w);
            *(uint2*)(Bs + r * ROWB + kv * 2) =
                make_uint2(*(uint32_t*)&h0, *(uint32_t*)&h1);
        }
    };

    constexpr int NT = K / 32;

    ldg_tile(0);
    sts_tile(0);
    __syncthreads();
    if (NT > 1) ldg_tile(32);

    for (int i = 0; i < NT; i++) {
        if (i + 1 < NT) sts_tile((i + 1) & 1);
        if (i + 2 < NT) ldg_tile((i + 2) * 32);

        const uint32_t stg = (uint32_t)((i & 1) * STAGE);
#pragma unroll
        for (int kk = 0; kk < 2; kk++) {              // two k16 steps
            const uint32_t ko = stg + kk * 32;        // 32B per k16 step
            uint32_t a[2][4], b[8][2];
#pragma unroll
            for (int mt = 0; mt < 2; mt++) {
                asm volatile(
                    "ldmatrix.sync.aligned.m8n8.x4.shared.b16 {%0,%1,%2,%3}, [%4];"
                    : "=r"(a[mt][0]), "=r"(a[mt][1]), "=r"(a[mt][2]), "=r"(a[mt][3])
                    : "r"(a_lm + ko + (uint32_t)(mt * 16 * ROWB)));
            }
#pragma unroll
            for (int np = 0; np < 4; np++) {          // nt pairs (0,1),(2,3),...
                asm volatile(
                    "ldmatrix.sync.aligned.m8n8.x4.shared.b16 {%0,%1,%2,%3}, [%4];"
                    : "=r"(b[np * 2][0]), "=r"(b[np * 2][1]),
                      "=r"(b[np * 2 + 1][0]), "=r"(b[np * 2 + 1][1])
                    : "r"(b_lm + ko + (uint32_t)(np * 16 * ROWB)));
            }
#pragma unroll
            for (int mt = 0; mt < 2; mt++)
#pragma unroll
                for (int nt = 0; nt < 8; nt++)
                    asm volatile(
                        "mma.sync.aligned.m16n8k16.row.col.f32.f16.f16.f32 "
                        "{%0,%1,%2,%3}, {%4,%5,%6,%7}, {%8,%9}, {%0,%1,%2,%3};\n"
                        : "+f"(acc[mt][nt][0]), "+f"(acc[mt][nt][1]),
                          "+f"(acc[mt][nt][2]), "+f"(acc[mt][nt][3])
                        : "r"(a[mt][0]), "r"(a[mt][1]), "r"(a[mt][2]), "r"(a[mt][3]),
                          "r"(b[nt][0]), "r"(b[nt][1]));
        }
        __syncthreads();
    }

    // ---- epilogue ----
#pragma unroll
    for (int mt = 0; mt < 2; mt++) {
        int row = bm + warpM * 32 + mt * 16 + g;
#pragma unroll
        for (int nt = 0; nt < 8; nt++) {
            int col = bn + warpN * 64 + nt * 8 + (t << 1);
            float bs0 = bias[col], bs1 = bias[col + 1];
            float v0 = acc[mt][nt][0] + bs0;
            float v1 = acc[mt][nt][1] + bs1;
            float v2 = acc[mt][nt][2] + bs0;
            float v3 = acc[mt][nt][3] + bs1;
            if (GELU) {
                __half* Hd = (__half*)g_hidden;
                __half2 h0 = __floats2half2_rn(gelu_exact(v0), gelu_exact(v1));
                __half2 h1 = __floats2half2_rn(gelu_exact(v2), gelu_exact(v3));
                *(uint32_t*)(Hd + (size_t)row * N + col)       = *(uint32_t*)&h0;
                *(uint32_t*)(Hd + (size_t)(row + 8) * N + col) = *(uint32_t*)&h1;
            } else {
                Cout[(size_t)row * N + col]           = v0;
                Cout[(size_t)row * N + col + 1]       = v1;
                Cout[(size_t)(row + 8) * N + col]     = v2;
                Cout[(size_t)(row + 8) * N + col + 1] = v3;
            }
        }
    }
}

// ---------------------------------------------------------------------------
extern "C" void kernel_launch(void* const* d_in, const int* in_sizes, int n_in,
                              void* d_out, int out_size)
{
    const float* u_t    = (const float*)d_in[0];
    const float* z_t    = (const float*)d_in[1];
    const float* prev   = (const float*)d_in[2];
    const float* prev_g = (const float*)d_in[3];
    const float* prev_b = (const float*)d_in[4];
    const float* u_g    = (const float*)d_in[5];
    const float* u_b    = (const float*)d_in[6];
    const float* z_g    = (const float*)d_in[7];
    const float* z_b    = (const float*)d_in[8];
    const float* W1     = (const float*)d_in[9];
    const float* b1     = (const float*)d_in[10];
    const float* W2     = (const float*)d_in[11];
    const float* b2     = (const float*)d_in[12];
    float* out = (float*)d_out;

    // 1) LN statistics
    ln_stats_kernel<<<dim3(MTOT, 3), 256>>>(prev, u_t, z_t);

    // 2) GEMM1: hidden(fp16) = gelu(LN-concat @ W1^T + b1)   [16384 x 512]
    gemm_fp16_kernel<true, true, CHID, KIN><<<dim3(CHID / 128, MTOT / 128), 256>>>(
        prev, u_t, z_t,
        prev_g, u_g, z_g,
        prev_b, u_b, z_b,
        W1, b1, nullptr);

    // 3) GEMM2: out = hidden @ W2^T + b2                     [16384 x 2048]
    gemm_fp16_kernel<false, false, HDIM, CHID><<<dim3(HDIM / 128, MTOT / 128), 256>>>(
        nullptr, nullptr, nullptr,
        nullptr, nullptr, nullptr,
        nullptr, nullptr, nullptr,
        W2, b2, out);
}

// round 11
// speedup vs baseline: 2.5916x; 1.1462x over previous
#include <cuda_runtime.h>
#include <cuda_fp16.h>
#include <cstdint>
#include <cstddef>

// Problem constants
#define MTOT 16384      // B*S = 4*4096
#define HDIM 2048       // H
#define CHID 512        // CH
#define KIN  6144       // 3*H

// Scratch: same proven global set (no big new globals -- module-load theory).
__device__ float2 g_stats[3 * MTOT];
__device__ float  g_hidden[(size_t)MTOT * CHID];   // used as fp16 via cast

__device__ __forceinline__ float gelu_exact(float x) {
    return 0.5f * x * (1.0f + erff(x * 0.70710678118654752440f));
}
__device__ __forceinline__ uint32_t smem_u32(const void* p) {
    uint32_t a;
    asm("{ .reg .u64 t; cvta.to.shared.u64 t, %1; cvt.u32.u64 %0, t; }" : "=r"(a) : "l"(p));
    return a;
}

// ---------------------------------------------------------------------------
// Kernel 1: per-row LayerNorm statistics (EXACT copy of the passing kernel)
// ---------------------------------------------------------------------------
__global__ void __launch_bounds__(256) ln_stats_kernel(
    const float* __restrict__ xp,
    const float* __restrict__ xu,
    const float* __restrict__ xz)
{
    const int m = blockIdx.x;
    const int t = blockIdx.y;
    const float* X = (t == 0) ? xp : ((t == 1) ? xu : xz);
    const float4* row = (const float4*)(X + (size_t)m * HDIM);

    float s = 0.f, sq = 0.f;
#pragma unroll
    for (int j = 0; j < 2; j++) {
        float4 v = row[threadIdx.x + j * 256];
        s  += v.x + v.y + v.z + v.w;
        sq += v.x * v.x + v.y * v.y + v.z * v.z + v.w * v.w;
    }

    __shared__ float s1[256], s2[256];
    s1[threadIdx.x] = s;
    s2[threadIdx.x] = sq;
    __syncthreads();
#pragma unroll
    for (int o = 128; o > 0; o >>= 1) {
        if (threadIdx.x < o) {
            s1[threadIdx.x] += s1[threadIdx.x + o];
            s2[threadIdx.x] += s2[threadIdx.x + o];
        }
        __syncthreads();
    }
    if (threadIdx.x == 0) {
        float mu  = s1[0] * (1.0f / HDIM);
        float var = s2[0] * (1.0f / HDIM) - mu * mu;
        g_stats[t * MTOT + m] = make_float2(mu, rsqrtf(var + 1e-5f));
    }
}

// ---------------------------------------------------------------------------
// fp16 mma GEMM, R9 skeleton with BK 32 -> 64.
//   * rows are 128B (64 halfs), XOR swizzle chunk' = chunk ^ (row&7), no pad
//   * 2-stage ping-pong in 64KB dynamic smem (opt-in attribute)
//   * one __syncthreads per 64-deep K tile (half as many barriers)
// BM=128, BN=128, 256 threads = 8 warps (4 M x 2 N),
// warp tile 32x64 = 2x8 m16n8k16 tiles, 4 k16-steps per BK tile.
// ---------------------------------------------------------------------------
#define A_ST  16384                    // 128 rows * 128 B
#define STAGE (2 * A_ST)               // A + B per stage = 32768 B
#define SMEMB (2 * STAGE)              // 65536 B dynamic

template<bool LN_A, bool GELU, int N, int K>
__global__ void __launch_bounds__(256) gemm_fp16_kernel(
    const float* __restrict__ x0, const float* __restrict__ x1, const float* __restrict__ x2,
    const float* __restrict__ g0, const float* __restrict__ g1, const float* __restrict__ g2,
    const float* __restrict__ c0, const float* __restrict__ c1, const float* __restrict__ c2,
    const float* __restrict__ W,      // [N][K] row-major fp32
    const float* __restrict__ bias,   // [N]
    float* __restrict__ Cout)         // [M][N] fp32
{
    extern __shared__ __align__(16) unsigned char smem[];

    const int bm   = blockIdx.y * 128;
    const int bn   = blockIdx.x * 128;
    const int tid  = threadIdx.x;
    const int lane = tid & 31;
    const int warp = tid >> 5;
    const int warpM = warp & 3;
    const int warpN = warp >> 2;
    const int g = lane >> 2;
    const int t = lane & 3;

    // staging geometry: 128 rows x 8 chunks(16B). r = tid>>3 (+j*32), c = tid&7
    const int rbase = tid >> 3;
    const int cchnk = tid & 7;

    const uint32_t sb = smem_u32(smem);

    // ldmatrix lane addressing (row-within-8 for swizzle == lane&7 on both sides)
    const int rowA = warpM * 32 + (lane & 15);       // + mt*16
    const int aSel = lane >> 4;                      // 16B half selector
    const int q    = lane >> 3;
    const int rowB = warpN * 64 + ((q >> 1) << 3) + (lane & 7);  // + np*16
    const int bSel = q & 1;
    const int sw7  = lane & 7;

    float acc[2][8][4];
#pragma unroll
    for (int i = 0; i < 2; i++)
#pragma unroll
        for (int j = 0; j < 8; j++)
#pragma unroll
            for (int r = 0; r < 4; r++) acc[i][j][r] = 0.f;

    // register tile buffers: per thread 4 rows x 1 chunk (8 values) each side
    float4 rXa[4], rXb[4], rWa[4], rWb[4];
    float4 rGa, rGb, rBa, rBb_;
    uint4  rXh[4];
    float2 rst[4];

    auto ldg_tile = [&](int k0) {
        const int kb = k0 + cchnk * 8;
        if (LN_A) {
            const int tt = kb >> 11;                  // tensor (2048-col blocks)
            const int kk = kb & 2047;
            const float* X  = (tt == 0) ? x0 : ((tt == 1) ? x1 : x2);
            const float* G  = (tt == 0) ? g0 : ((tt == 1) ? g1 : g2);
            const float* Bb = (tt == 0) ? c0 : ((tt == 1) ? c1 : c2);
            rGa  = *(const float4*)(G + kk);
            rGb  = *(const float4*)(G + kk + 4);
            rBa  = *(const float4*)(Bb + kk);
            rBb_ = *(const float4*)(Bb + kk + 4);
#pragma unroll
            for (int j = 0; j < 4; j++) {
                const int m = bm + rbase + j * 32;
                rst[j] = g_stats[tt * MTOT + m];
                rXa[j] = *(const float4*)(X + (size_t)m * HDIM + kk);
                rXb[j] = *(const float4*)(X + (size_t)m * HDIM + kk + 4);
            }
        } else {
            const __half* Ah = (const __half*)g_hidden;
#pragma unroll
            for (int j = 0; j < 4; j++) {
                const int m = bm + rbase + j * 32;
                rXh[j] = *(const uint4*)(Ah + (size_t)m * K + kb);
            }
        }
#pragma unroll
        for (int j = 0; j < 4; j++) {
            const int n = bn + rbase + j * 32;
            rWa[j] = *(const float4*)(W + (size_t)n * K + kb);
            rWb[j] = *(const float4*)(W + (size_t)n * K + kb + 4);
        }
    };

    auto sts_tile = [&](int buf) {
        const uint32_t As = sb + buf * STAGE;
        const uint32_t Bs = As + A_ST;
#pragma unroll
        for (int j = 0; j < 4; j++) {
            const int r = rbase + j * 32;
            const uint32_t off = (uint32_t)(r * 128 + ((cchnk ^ (r & 7)) << 4));
            if (LN_A) {
                float4 va = rXa[j], vb = rXb[j];
                const float mu = rst[j].x, rs = rst[j].y;
                va.x = (va.x - mu) * rs * rGa.x + rBa.x;
                va.y = (va.y - mu) * rs * rGa.y + rBa.y;
                va.z = (va.z - mu) * rs * rGa.z + rBa.z;
                va.w = (va.w - mu) * rs * rGa.w + rBa.w;
                vb.x = (vb.x - mu) * rs * rGb.x + rBb_.x;
                vb.y = (vb.y - mu) * rs * rGb.y + rBb_.y;
                vb.z = (vb.z - mu) * rs * rGb.z + rBb_.z;
                vb.w = (vb.w - mu) * rs * rGb.w + rBb_.w;
                __half2 h0 = __floats2half2_rn(va.x, va.y);
                __half2 h1 = __floats2half2_rn(va.z, va.w);
                __half2 h2 = __floats2half2_rn(vb.x, vb.y);
                __half2 h3 = __floats2half2_rn(vb.z, vb.w);
                uint4 u = make_uint4(*(uint32_t*)&h0, *(uint32_t*)&h1,
                                     *(uint32_t*)&h2, *(uint32_t*)&h3);
                *(uint4*)(smem + (As - sb) + off) = u;
            } else {
                *(uint4*)(smem + (As - sb) + off) = rXh[j];
            }
        }
#pragma unroll
        for (int j = 0; j < 4; j++) {
            const int r = rbase + j * 32;
            const uint32_t off = (uint32_t)(r * 128 + ((cchnk ^ (r & 7)) << 4));
            float4 va = rWa[j], vb = rWb[j];
            __half2 h0 = __floats2half2_rn(va.x, va.y);
            __half2 h1 = __floats2half2_rn(va.z, va.w);
            __half2 h2 = __floats2half2_rn(vb.x, vb.y);
            __half2 h3 = __floats2half2_rn(vb.z, vb.w);
            uint4 u = make_uint4(*(uint32_t*)&h0, *(uint32_t*)&h1,
                                 *(uint32_t*)&h2, *(uint32_t*)&h3);
            *(uint4*)(smem + (Bs - sb) + off) = u;
        }
    };

    constexpr int NT = K / 64;

    ldg_tile(0);
    sts_tile(0);
    __syncthreads();
    if (NT > 1) ldg_tile(64);

    for (int i = 0; i < NT; i++) {
        if (i + 1 < NT) sts_tile((i + 1) & 1);
        if (i + 2 < NT) ldg_tile((i + 2) * 64);

        const uint32_t stg = (uint32_t)((i & 1) * STAGE);
#pragma unroll
        for (int kk = 0; kk < 4; kk++) {              // four k16 steps
            uint32_t a[2][4], b[8][2];
            const uint32_t aswz = (uint32_t)((((kk * 2 + aSel) ^ sw7) & 7) << 4);
            const uint32_t bswz = (uint32_t)((((kk * 2 + bSel) ^ sw7) & 7) << 4);
#pragma unroll
            for (int mt = 0; mt < 2; mt++) {
                asm volatile(
                    "ldmatrix.sync.aligned.m8n8.x4.shared.b16 {%0,%1,%2,%3}, [%4];"
                    : "=r"(a[mt][0]), "=r"(a[mt][1]), "=r"(a[mt][2]), "=r"(a[mt][3])
                    : "r"(sb + stg + (uint32_t)((rowA + mt * 16) * 128) + aswz));
            }
#pragma unroll
            for (int np = 0; np < 4; np++) {
                asm volatile(
                    "ldmatrix.sync.aligned.m8n8.x4.shared.b16 {%0,%1,%2,%3}, [%4];"
                    : "=r"(b[np * 2][0]), "=r"(b[np * 2][1]),
                      "=r"(b[np * 2 + 1][0]), "=r"(b[np * 2 + 1][1])
                    : "r"(sb + A_ST + stg + (uint32_t)((rowB + np * 16) * 128) + bswz));
            }
#pragma unroll
            for (int mt = 0; mt < 2; mt++)
#pragma unroll
                for (int nt = 0; nt < 8; nt++)
                    asm volatile(
                        "mma.sync.aligned.m16n8k16.row.col.f32.f16.f16.f32 "
                        "{%0,%1,%2,%3}, {%4,%5,%6,%7}, {%8,%9}, {%0,%1,%2,%3};\n"
                        : "+f"(acc[mt][nt][0]), "+f"(acc[mt][nt][1]),
                          "+f"(acc[mt][nt][2]), "+f"(acc[mt][nt][3])
                        : "r"(a[mt][0]), "r"(a[mt][1]), "r"(a[mt][2]), "r"(a[mt][3]),
                          "r"(b[nt][0]), "r"(b[nt][1]));
        }
        __syncthreads();
    }

    // ---- epilogue (identical to R9) ----
#pragma unroll
    for (int mt = 0; mt < 2; mt++) {
        int row = bm + warpM * 32 + mt * 16 + g;
#pragma unroll
        for (int nt = 0; nt < 8; nt++) {
            int col = bn + warpN * 64 + nt * 8 + (t << 1);
            float bs0 = bias[col], bs1 = bias[col + 1];
            float v0 = acc[mt][nt][0] + bs0;
            float v1 = acc[mt][nt][1] + bs1;
            float v2 = acc[mt][nt][2] + bs0;
            float v3 = acc[mt][nt][3] + bs1;
            if (GELU) {
                __half* Hd = (__half*)g_hidden;
                __half2 h0 = __floats2half2_rn(gelu_exact(v0), gelu_exact(v1));
                __half2 h1 = __floats2half2_rn(gelu_exact(v2), gelu_exact(v3));
                *(uint32_t*)(Hd + (size_t)row * N + col)       = *(uint32_t*)&h0;
                *(uint32_t*)(Hd + (size_t)(row + 8) * N + col) = *(uint32_t*)&h1;
            } else {
                Cout[(size_t)row * N + col]           = v0;
                Cout[(size_t)row * N + col + 1]       = v1;
                Cout[(size_t)(row + 8) * N + col]     = v2;
                Cout[(size_t)(row + 8) * N + col + 1] = v3;
            }
        }
    }
}

// ---------------------------------------------------------------------------
extern "C" void kernel_launch(void* const* d_in, const int* in_sizes, int n_in,
                              void* d_out, int out_size)
{
    const float* u_t    = (const float*)d_in[0];
    const float* z_t    = (const float*)d_in[1];
    const float* prev   = (const float*)d_in[2];
    const float* prev_g = (const float*)d_in[3];
    const float* prev_b = (const float*)d_in[4];
    const float* u_g    = (const float*)d_in[5];
    const float* u_b    = (const float*)d_in[6];
    const float* z_g    = (const float*)d_in[7];
    const float* z_b    = (const float*)d_in[8];
    const float* W1     = (const float*)d_in[9];
    const float* b1     = (const float*)d_in[10];
    const float* W2     = (const float*)d_in[11];
    const float* b2     = (const float*)d_in[12];
    float* out = (float*)d_out;

    cudaFuncSetAttribute(gemm_fp16_kernel<true,  true,  CHID, KIN>,
                         cudaFuncAttributeMaxDynamicSharedMemorySize, SMEMB);
    cudaFuncSetAttribute(gemm_fp16_kernel<false, false, HDIM, CHID>,
                         cudaFuncAttributeMaxDynamicSharedMemorySize, SMEMB);

    // 1) LN statistics
    ln_stats_kernel<<<dim3(MTOT, 3), 256>>>(prev, u_t, z_t);

    // 2) GEMM1: hidden(fp16) = gelu(LN-concat @ W1^T + b1)   [16384 x 512]
    gemm_fp16_kernel<true, true, CHID, KIN>
        <<<dim3(CHID / 128, MTOT / 128), 256, SMEMB>>>(
        prev, u_t, z_t,
        prev_g, u_g, z_g,
        prev_b, u_b, z_b,
        W1, b1, nullptr);

    // 3) GEMM2: out = hidden @ W2^T + b2                     [16384 x 2048]
    gemm_fp16_kernel<false, false, HDIM, CHID>
        <<<dim3(HDIM / 128, MTOT / 128), 256, SMEMB>>>(
        nullptr, nullptr, nullptr,
        nullptr, nullptr, nullptr,
        nullptr, nullptr, nullptr,
        W2, b2, out);
}